// round 11
// baseline (speedup 1.0000x reference)
#include <cuda_runtime.h>
#include <cstdint>

#define BB   4
#define CC   256
#define HH   64
#define WW   64
#define HWS  4096
#define NP   9
#define OCH  18
#define OPL  256
#define KTOT 2304
#define MTOT 16384        // B*H*W

#define MT     128        // GEMM M tile
#define NCHUNK 72         // K chunks of 32, kg' = k*256 + c ordering
#define NTH    512
#define MST    136        // sA row stride (floats), K-major
#define BST    40         // sB row stride (floats) — conflict-free LDS.64 frags
#define NSTAGE 3

// ---- dynamic smem for GEMM: 3 x (A 32x136 + B 256x40) ----
#define SA_BYTES (32 * MST * 4)            // 17408
#define SB_BYTES (256 * BST * 4)           // 40960
#define SM_SB0   (NSTAGE * SA_BYTES)       // 52224
#define SM_TOTAL (NSTAGE * (SA_BYTES + SB_BYTES))   // 175104

__device__ float4 g_mw[BB * HWS * NP];
__device__ int4   g_mi[BB * HWS * NP];
__device__ float  g_wB2[OPL * KTOT];       // [n][chunk*32 + pairperm], tf32
__device__ float  g_A[(size_t)KTOT * MTOT];// A^T: [kg'][pos], tf32 samples

typedef unsigned long long ull;

// ---------------------------------------------------------------------------
// helpers
// ---------------------------------------------------------------------------
__device__ __forceinline__ float tf32r(float x) {
    uint32_t u;
    asm("cvt.rna.tf32.f32 %0, %1;" : "=r"(u) : "f"(x));
    return __uint_as_float(u);
}
__device__ __forceinline__ ull dup2(float v) {
    ull r; asm("mov.b64 %0, {%1, %1};" : "=l"(r) : "f"(v)); return r;
}
__device__ __forceinline__ ull pack2(float a, float b) {
    ull r; asm("mov.b64 %0, {%1, %2};" : "=l"(r) : "f"(a), "f"(b)); return r;
}
__device__ __forceinline__ void fma2(ull& acc, ull a, ull b) {
    asm("fma.rn.f32x2 %0, %1, %2, %0;" : "+l"(acc) : "l"(a), "l"(b));
}
union UPair { ull u; float2 f; };

__device__ __forceinline__ uint32_t smem_u32(const void* p) {
    return (uint32_t)__cvta_generic_to_shared(p);
}
__device__ __forceinline__ void cpa16(void* dst, const void* src) {
    asm volatile("cp.async.cg.shared.global [%0], [%1], 16;"
                 :: "r"(smem_u32(dst)), "l"(src));
}
__device__ __forceinline__ void cpa_commit() {
    asm volatile("cp.async.commit_group;" ::: "memory");
}
template <int N>
__device__ __forceinline__ void cpa_wait_group() {
    asm volatile("cp.async.wait_group %0;" :: "n"(N) : "memory");
}

__device__ __forceinline__ void mma_tf32(float* c, const uint32_t* a, const uint32_t* b) {
    asm volatile(
        "mma.sync.aligned.m16n8k8.row.col.f32.tf32.tf32.f32 "
        "{%0,%1,%2,%3}, {%4,%5,%6,%7}, {%8,%9}, {%0,%1,%2,%3};"
        : "+f"(c[0]), "+f"(c[1]), "+f"(c[2]), "+f"(c[3])
        : "r"(a[0]), "r"(a[1]), "r"(a[2]), "r"(a[3]), "r"(b[0]), "r"(b[1]));
}

__device__ __forceinline__ float dot4(float4 wv, const float* xp, int4 iv) {
    return wv.x * xp[iv.x] + wv.y * xp[iv.y] + wv.z * xp[iv.z] + wv.w * xp[iv.w];
}

// ---------------------------------------------------------------------------
// Kernel 1 (fused prep):
//   blocks [0,128):  offsets conv via smem-staged x tiles + f32x2 FMA
//   blocks [128+):   permute+tf32-round+pair-interleave w_conv -> g_wB2
// ---------------------------------------------------------------------------
__global__ __launch_bounds__(512) void prep_kernel(const float* __restrict__ x,
                                                   const float* __restrict__ w_p,
                                                   const float* __restrict__ wc)
{
    if (blockIdx.x >= 128) {
        int idx = (blockIdx.x - 128) * 512 + threadIdx.x;   // PHYSICAL slot
        if (idx < OPL * KTOT) {
            int n  = idx / KTOT;
            int rp = idx - n * KTOT;
            int chunk = rp >> 5;
            int p  = rp & 31;
            int g  = p >> 3;
            int pp = p & 7;
            int t  = (pp >> 1) + ((pp & 1) << 2);   // inverse of phys=2*(t&3)+(t>>2)
            int c  = (chunk & 7) * 32 + g * 8 + t;
            int k  = chunk >> 3;
            g_wB2[idx] = tf32r(wc[n * KTOT + c * 9 + k]);
        }
        return;
    }

    // 36864 B union:
    //   staging: s_x 4224 floats (2112 ull) + s_wp 1440 ull
    //   reduce:  s_red [4][128][9] ull (4608 ull)
    __shared__ ull s_mem[4608];
    float* s_x  = (float*)s_mem;        // [16ch][4 rows][66 cols]
    ull*   s_wp = s_mem + 2112;         // [(cl*9+t)*10 + op]

    const int tid   = threadIdx.x;
    const int pos_l = tid & 127;
    const int part  = tid >> 7;                 // 0..3
    const int pos   = blockIdx.x * 128 + pos_l;
    const int b  = pos >> 12;
    const int h0 = ((blockIdx.x * 128) >> 6) & 63;   // first of 2 rows
    const int hh = pos_l >> 6;                  // 0..1
    const int h  = (pos >> 6) & 63;
    const int w  = pos & 63;
    const float* xb = x + (size_t)b * CC * HWS;

    ull accp[9];
#pragma unroll
    for (int i = 0; i < 9; i++) accp[i] = 0ull;

    for (int c16 = 0; c16 < 16; c16++) {
        __syncthreads();
        // ---- stage x: 16 ch x 4 rows x 66 cols, zero-padded halo ----
        for (int idx = tid; idx < 16 * 264; idx += 512) {
            int c   = idx / 264;
            int rem = idx - c * 264;
            int r   = rem / 66;
            int col = rem - r * 66;
            int gh = h0 - 1 + r;
            int gw = col - 1;
            float v = 0.f;
            if ((unsigned)gh < 64u && (unsigned)gw < 64u)
                v = xb[(size_t)(c16 * 16 + c) * HWS + gh * 64 + gw];
            s_x[idx] = v;
        }
        // ---- stage weights: 16 ch x 9 taps x 9 op-pairs ----
        for (int idx = tid; idx < 16 * 81; idx += 512) {
            int cl = idx / 81;
            int r  = idx - cl * 81;
            int t  = r / 9;
            int op = r - t * 9;
            int c  = c16 * 16 + cl;
            s_wp[(cl * 9 + t) * 10 + op] =
                pack2(w_p[((2 * op)     * CC + c) * 9 + t],
                      w_p[((2 * op + 1) * CC + c) * 9 + t]);
        }
        __syncthreads();

#pragma unroll
        for (int q = 0; q < 4; q++) {
            int cl = part * 4 + q;
            const float* xs = s_x + cl * 264 + hh * 66 + w;
            float xv[9];
#pragma unroll
            for (int t = 0; t < 9; t++)
                xv[t] = xs[(t / 3) * 66 + (t % 3)];
#pragma unroll
            for (int t = 0; t < 9; t++) {
                ull xd = dup2(xv[t]);
                const ulonglong2* wp4 = (const ulonglong2*)&s_wp[(cl * 9 + t) * 10];
                ulonglong2 p01 = wp4[0];
                ulonglong2 p23 = wp4[1];
                ulonglong2 p45 = wp4[2];
                ulonglong2 p67 = wp4[3];
                ull p8 = s_wp[(cl * 9 + t) * 10 + 8];
                fma2(accp[0], p01.x, xd);
                fma2(accp[1], p01.y, xd);
                fma2(accp[2], p23.x, xd);
                fma2(accp[3], p23.y, xd);
                fma2(accp[4], p45.x, xd);
                fma2(accp[5], p45.y, xd);
                fma2(accp[6], p67.x, xd);
                fma2(accp[7], p67.y, xd);
                fma2(accp[8], p8,    xd);
            }
        }
    }

    __syncthreads();
    ull* s_red = s_mem;   // [part][pos_l][9]
#pragma unroll
    for (int op = 0; op < 9; op++)
        s_red[(part * 128 + pos_l) * 9 + op] = accp[op];
    __syncthreads();

    if (tid < 128) {
        float acc[OCH];
#pragma unroll
        for (int op = 0; op < 9; op++) {
            UPair u0, u1, u2, u3;
            u0.u = s_red[(0 * 128 + tid) * 9 + op];
            u1.u = s_red[(1 * 128 + tid) * 9 + op];
            u2.u = s_red[(2 * 128 + tid) * 9 + op];
            u3.u = s_red[(3 * 128 + tid) * 9 + op];
            acc[2 * op]     = u0.f.x + u1.f.x + u2.f.x + u3.f.x;
            acc[2 * op + 1] = u0.f.y + u1.f.y + u2.f.y + u3.f.y;
        }
#pragma unroll
        for (int k = 0; k < 9; k++) {
            float rx = (float)(k / 3 - 1);
            float ry = (float)(k % 3 - 1);
            float px = acc[k]     + rx + (float)(h + 1);
            float py = acc[9 + k] + ry + (float)(w + 1);
            float fx = floorf(px), fy = floorf(py);
            float ltx = fminf(fmaxf(fx,       0.f), 63.f);
            float lty = fminf(fmaxf(fy,       0.f), 63.f);
            float rbx = fminf(fmaxf(fx + 1.f, 0.f), 63.f);
            float rby = fminf(fmaxf(fy + 1.f, 0.f), 63.f);
            float pxc = fminf(fmaxf(px,       0.f), 63.f);
            float pyc = fminf(fmaxf(py,       0.f), 63.f);
            float glt = (1.f + (ltx - pxc)) * (1.f + (lty - pyc));
            float grb = (1.f - (rbx - pxc)) * (1.f - (rby - pyc));
            float glb = (1.f + (ltx - pxc)) * (1.f - (rby - pyc));
            float grt = (1.f - (rbx - pxc)) * (1.f + (lty - pyc));
            int iltx = (int)ltx, ilty = (int)lty, irbx = (int)rbx, irby = (int)rby;
            g_mw[pos * 9 + k] = make_float4(glt, grb, glb, grt);
            g_mi[pos * 9 + k] = make_int4(iltx * WW + ilty,
                                          irbx * WW + irby,
                                          iltx * WW + irby,
                                          irbx * WW + ilty);
        }
    }
}

// ---------------------------------------------------------------------------
// Kernel 2: gather — materialize A^T[kg'][pos] (tf32 bilinear samples)
// ---------------------------------------------------------------------------
__global__ __launch_bounds__(1024) void gather_kernel(const float* __restrict__ x)
{
    const int tid  = threadIdx.x;
    const int warp = tid >> 5;
    const int lane = tid & 31;
    const int pw   = warp & 3;
    const int cs   = warp >> 2;
    const int pos  = blockIdx.x * 128 + pw * 32 + lane;
    const int b    = pos >> 12;
    const float* xb = x + (size_t)b * CC * HWS;

#pragma unroll
    for (int k = 0; k < 9; k++) {
        const float4 wv = g_mw[pos * NP + k];
        const int4   iv = g_mi[pos * NP + k];
        const int kg0 = k * 256 + cs * 32;
        float* op = g_A + (size_t)kg0 * MTOT + pos;
        const float* xp = xb + (size_t)(cs * 32) * HWS;
#pragma unroll 8
        for (int j = 0; j < 32; j++) {
            op[(size_t)j * MTOT] = tf32r(dot4(wv, xp + (size_t)j * HWS, iv));
        }
    }
}

// ---------------------------------------------------------------------------
// Kernel 3: dense tf32 GEMM, 3-stage cp.async pipeline
//   A smem K-major [32][136]; B [256][40] pair-interleaved (LDS.64 frags)
// ---------------------------------------------------------------------------
__global__ void __launch_bounds__(NTH, 1) gemm_kernel(float* __restrict__ out)
{
    extern __shared__ char smem[];

    const int tid  = threadIdx.x;
    const int wid  = tid >> 5;
    const int lane = tid & 31;
    const int gid  = lane >> 2;
    const int tig  = lane & 3;
    const int p0   = blockIdx.x * MT;
    const int b    = p0 >> 12;
    const int m0   = p0;

    const int mBase = (wid & 3) * 32;
    const int nBase = (wid >> 2) * 64;

    auto issue_stage = [&](int i, int s) {
        char* sa = smem + s * SA_BYTES;
        char* sb = smem + SM_SB0 + s * SB_BYTES;
        const size_t kg0 = (size_t)i * 32;
        // A: 32 rows x 128 floats
#pragma unroll
        for (int r = 0; r < 2; r++) {
            int id = tid + r * NTH;
            int kr = id >> 5;
            int q  = id & 31;
            cpa16(sa + kr * (MST * 4) + q * 16,
                  g_A + (kg0 + kr) * MTOT + m0 + q * 4);
        }
        // B: 256 rows x 32 floats (already pair-interleaved in global)
#pragma unroll
        for (int r = 0; r < 4; r++) {
            int id = tid + r * NTH;
            int nr = id >> 3;
            int q  = id & 7;
            cpa16(sb + nr * (BST * 4) + q * 16,
                  g_wB2 + (size_t)nr * KTOT + kg0 + q * 4);
        }
        cpa_commit();
    };

    float acc[2][8][4];
#pragma unroll
    for (int mf = 0; mf < 2; mf++)
#pragma unroll
        for (int nf = 0; nf < 8; nf++)
#pragma unroll
            for (int r = 0; r < 4; r++) acc[mf][nf][r] = 0.f;

    issue_stage(0, 0);
    issue_stage(1, 1);

    for (int i = 0; i < NCHUNK; i++) {
        const int s = i % NSTAGE;
        cpa_wait_group<1>();
        __syncthreads();

        if (i + 2 < NCHUNK) issue_stage(i + 2, (i + 2) % NSTAGE);
        else                cpa_commit();

        const uint32_t* sAu = (const uint32_t*)(smem + s * SA_BYTES);
        const float*    sBf = (const float*)(smem + SM_SB0 + s * SB_BYTES);
#pragma unroll
        for (int ks = 0; ks < 4; ks++) {
            const int kr0 = ks * 8 + tig;
            uint32_t a[2][4], bfrag[8][2];
#pragma unroll
            for (int mf = 0; mf < 2; mf++) {
                int m = mBase + mf * 16 + gid;
                a[mf][0] = sAu[kr0 * MST + m];
                a[mf][1] = sAu[kr0 * MST + m + 8];
                a[mf][2] = sAu[(kr0 + 4) * MST + m];
                a[mf][3] = sAu[(kr0 + 4) * MST + m + 8];
            }
#pragma unroll
            for (int nf = 0; nf < 8; nf++) {
                int n = nBase + nf * 8 + gid;
                float2 bv = *(const float2*)&sBf[n * BST + ks * 8 + 2 * tig];
                bfrag[nf][0] = __float_as_uint(bv.x);
                bfrag[nf][1] = __float_as_uint(bv.y);
            }
#pragma unroll
            for (int mf = 0; mf < 2; mf++)
#pragma unroll
                for (int nf = 0; nf < 8; nf++)
                    mma_tf32(acc[mf][nf], a[mf], bfrag[nf]);
        }
    }

    // ---- epilogue ----
    {
        const int hw0 = p0 & 4095;
        float* ob = out + (size_t)b * OPL * HWS + hw0;
#pragma unroll
        for (int mf = 0; mf < 2; mf++) {
            int m = mBase + mf * 16 + gid;
#pragma unroll
            for (int nf = 0; nf < 8; nf++) {
                int n = nBase + nf * 8 + 2 * tig;
                ob[(size_t)n * HWS + m]           = acc[mf][nf][0];
                ob[(size_t)(n + 1) * HWS + m]     = acc[mf][nf][1];
                ob[(size_t)n * HWS + m + 8]       = acc[mf][nf][2];
                ob[(size_t)(n + 1) * HWS + m + 8] = acc[mf][nf][3];
            }
        }
    }
}

// ---------------------------------------------------------------------------
extern "C" void kernel_launch(void* const* d_in, const int* in_sizes, int n_in,
                              void* d_out, int out_size)
{
    const float* x      = (const float*)d_in[0];   // (4,256,64,64)
    const float* w_p    = (const float*)d_in[1];   // (18,256,3,3)
    const float* w_conv = (const float*)d_in[2];   // (256,256,3,3)
    float* out = (float*)d_out;                    // (4,256,64,64)

    cudaFuncSetAttribute(gemm_kernel, cudaFuncAttributeMaxDynamicSharedMemorySize, SM_TOTAL);

    const int permBlocks = (OPL * KTOT + 511) / 512;
    prep_kernel<<<128 + permBlocks, 512>>>(x, w_p, w_conv);
    gather_kernel<<<MTOT / 128, 1024>>>(x);
    gemm_kernel<<<MTOT / MT, NTH, SM_TOTAL>>>(out);
}

// round 12
// speedup vs baseline: 1.0560x; 1.0560x over previous
#include <cuda_runtime.h>
#include <cstdint>

#define BB   4
#define CC   256
#define HH   64
#define WW   64
#define HWS  4096
#define NP   9
#define OCH  18
#define OPL  256
#define KTOT 2304
#define MTOT 16384        // B*H*W

#define MT     128        // GEMM M tile
#define NCHUNK 72         // K chunks of 32, kg' = k*256 + c ordering
#define NTH    512
#define PRST   264        // sA pair-row stride (floats): addr8 mod16 = 4*tig+gid
#define BST    40         // sB row stride (floats)
#define NSTAGE 3

// ---- dynamic smem for GEMM: 3 x (A 16x264 + B 256x40) ----
#define SA_BYTES (16 * PRST * 4)           // 16896
#define SB_BYTES (256 * BST * 4)           // 40960
#define SM_SB0   (NSTAGE * SA_BYTES)       // 50688
#define SM_TOTAL (NSTAGE * (SA_BYTES + SB_BYTES))   // 173568

__device__ float4 g_mw[BB * HWS * NP];
__device__ int4   g_mi[BB * HWS * NP];
__device__ float  g_wB2[OPL * KTOT];       // [n][chunk*32 + pairperm], tf32
// A interleaved: [chunk][pr(16)][pos][slot(2)], tf32 samples
__device__ float  g_A[(size_t)KTOT * MTOT];

typedef unsigned long long ull;

// ---------------------------------------------------------------------------
// helpers
// ---------------------------------------------------------------------------
__device__ __forceinline__ float tf32r(float x) {
    uint32_t u;
    asm("cvt.rna.tf32.f32 %0, %1;" : "=r"(u) : "f"(x));
    return __uint_as_float(u);
}
__device__ __forceinline__ ull dup2(float v) {
    ull r; asm("mov.b64 %0, {%1, %1};" : "=l"(r) : "f"(v)); return r;
}
__device__ __forceinline__ ull pack2(float a, float b) {
    ull r; asm("mov.b64 %0, {%1, %2};" : "=l"(r) : "f"(a), "f"(b)); return r;
}
__device__ __forceinline__ void fma2(ull& acc, ull a, ull b) {
    asm("fma.rn.f32x2 %0, %1, %2, %0;" : "+l"(acc) : "l"(a), "l"(b));
}
union UPair { ull u; float2 f; };

__device__ __forceinline__ uint32_t smem_u32(const void* p) {
    return (uint32_t)__cvta_generic_to_shared(p);
}
__device__ __forceinline__ void cpa16(void* dst, const void* src) {
    asm volatile("cp.async.cg.shared.global [%0], [%1], 16;"
                 :: "r"(smem_u32(dst)), "l"(src));
}
__device__ __forceinline__ void cpa_commit() {
    asm volatile("cp.async.commit_group;" ::: "memory");
}
template <int N>
__device__ __forceinline__ void cpa_wait_group() {
    asm volatile("cp.async.wait_group %0;" :: "n"(N) : "memory");
}

__device__ __forceinline__ void mma_tf32(float* c, const uint32_t* a, const uint32_t* b) {
    asm volatile(
        "mma.sync.aligned.m16n8k8.row.col.f32.tf32.tf32.f32 "
        "{%0,%1,%2,%3}, {%4,%5,%6,%7}, {%8,%9}, {%0,%1,%2,%3};"
        : "+f"(c[0]), "+f"(c[1]), "+f"(c[2]), "+f"(c[3])
        : "r"(a[0]), "r"(a[1]), "r"(a[2]), "r"(a[3]), "r"(b[0]), "r"(b[1]));
}

__device__ __forceinline__ float dot4(float4 wv, const float* xp, int4 iv) {
    return wv.x * xp[iv.x] + wv.y * xp[iv.y] + wv.z * xp[iv.z] + wv.w * xp[iv.w];
}

// ---------------------------------------------------------------------------
// Kernel 1 (fused prep): offsets conv + metadata (blocks 0..127),
//                        w_conv permute+pair-interleave+tf32 (blocks 128+)
// ---------------------------------------------------------------------------
__global__ __launch_bounds__(512) void prep_kernel(const float* __restrict__ x,
                                                   const float* __restrict__ w_p,
                                                   const float* __restrict__ wc)
{
    if (blockIdx.x >= 128) {
        int idx = (blockIdx.x - 128) * 512 + threadIdx.x;   // PHYSICAL slot
        if (idx < OPL * KTOT) {
            int n  = idx / KTOT;
            int rp = idx - n * KTOT;
            int chunk = rp >> 5;
            int p  = rp & 31;
            int g  = p >> 3;
            int pp = p & 7;
            int t  = (pp >> 1) + ((pp & 1) << 2);   // inverse of phys=2*(t&3)+(t>>2)
            int c  = (chunk & 7) * 32 + g * 8 + t;
            int k  = chunk >> 3;
            g_wB2[idx] = tf32r(wc[n * KTOT + c * 9 + k]);
        }
        return;
    }

    __shared__ ull s_mem[64 * 9 * 10];

    const int tid   = threadIdx.x;
    const int pos_l = tid & 127;
    const int part  = tid >> 7;
    const int pos   = blockIdx.x * 128 + pos_l;
    const int b = pos >> 12;
    const int h = (pos >> 6) & 63;
    const int w = pos & 63;
    const float* xb = x + (size_t)b * CC * HWS;

    ull accp[9];
#pragma unroll
    for (int i = 0; i < 9; i++) accp[i] = 0ull;

    for (int blk = 0; blk < 4; blk++) {
        __syncthreads();
        for (int i = tid; i < 64 * 81; i += 512) {
            int cl = i / 81;
            int r  = i % 81;
            int t  = r / 9;
            int op = r - t * 9;
            int c  = blk * 64 + cl;
            float w0 = w_p[((2 * op)     * CC + c) * 9 + t];
            float w1 = w_p[((2 * op + 1) * CC + c) * 9 + t];
            s_mem[(cl * 9 + t) * 10 + op] = pack2(w0, w1);
        }
        __syncthreads();

        for (int q = 0; q < 16; q++) {
            int cl = part * 16 + q;
            const float* xp = xb + (size_t)(blk * 64 + cl) * HWS;
            float xv[9];
#pragma unroll
            for (int dh = -1; dh <= 1; dh++) {
#pragma unroll
                for (int dw = -1; dw <= 1; dw++) {
                    int hh = h + dh, ww = w + dw;
                    float v = 0.f;
                    if (hh >= 0 && hh < HH && ww >= 0 && ww < WW) v = xp[hh * WW + ww];
                    xv[(dh + 1) * 3 + (dw + 1)] = v;
                }
            }
#pragma unroll
            for (int t = 0; t < 9; t++) {
                ull xd = dup2(xv[t]);
                const ulonglong2* wp4 = (const ulonglong2*)&s_mem[(cl * 9 + t) * 10];
                ulonglong2 p01 = wp4[0];
                ulonglong2 p23 = wp4[1];
                ulonglong2 p45 = wp4[2];
                ulonglong2 p67 = wp4[3];
                ull p8 = s_mem[(cl * 9 + t) * 10 + 8];
                fma2(accp[0], p01.x, xd);
                fma2(accp[1], p01.y, xd);
                fma2(accp[2], p23.x, xd);
                fma2(accp[3], p23.y, xd);
                fma2(accp[4], p45.x, xd);
                fma2(accp[5], p45.y, xd);
                fma2(accp[6], p67.x, xd);
                fma2(accp[7], p67.y, xd);
                fma2(accp[8], p8,    xd);
            }
        }
    }

    __syncthreads();
    ull* s_red = s_mem;
#pragma unroll
    for (int op = 0; op < 9; op++)
        s_red[(part * 128 + pos_l) * 9 + op] = accp[op];
    __syncthreads();

    if (tid < 128) {
        float acc[OCH];
#pragma unroll
        for (int op = 0; op < 9; op++) {
            UPair u0, u1, u2, u3;
            u0.u = s_red[(0 * 128 + tid) * 9 + op];
            u1.u = s_red[(1 * 128 + tid) * 9 + op];
            u2.u = s_red[(2 * 128 + tid) * 9 + op];
            u3.u = s_red[(3 * 128 + tid) * 9 + op];
            acc[2 * op]     = u0.f.x + u1.f.x + u2.f.x + u3.f.x;
            acc[2 * op + 1] = u0.f.y + u1.f.y + u2.f.y + u3.f.y;
        }
#pragma unroll
        for (int k = 0; k < 9; k++) {
            float rx = (float)(k / 3 - 1);
            float ry = (float)(k % 3 - 1);
            float px = acc[k]     + rx + (float)(h + 1);
            float py = acc[9 + k] + ry + (float)(w + 1);
            float fx = floorf(px), fy = floorf(py);
            float ltx = fminf(fmaxf(fx,       0.f), 63.f);
            float lty = fminf(fmaxf(fy,       0.f), 63.f);
            float rbx = fminf(fmaxf(fx + 1.f, 0.f), 63.f);
            float rby = fminf(fmaxf(fy + 1.f, 0.f), 63.f);
            float pxc = fminf(fmaxf(px,       0.f), 63.f);
            float pyc = fminf(fmaxf(py,       0.f), 63.f);
            float glt = (1.f + (ltx - pxc)) * (1.f + (lty - pyc));
            float grb = (1.f - (rbx - pxc)) * (1.f - (rby - pyc));
            float glb = (1.f + (ltx - pxc)) * (1.f - (rby - pyc));
            float grt = (1.f - (rbx - pxc)) * (1.f + (lty - pyc));
            int iltx = (int)ltx, ilty = (int)lty, irbx = (int)rbx, irby = (int)rby;
            g_mw[pos * 9 + k] = make_float4(glt, grb, glb, grt);
            g_mi[pos * 9 + k] = make_int4(iltx * WW + ilty,
                                          irbx * WW + irby,
                                          iltx * WW + irby,
                                          irbx * WW + ilty);
        }
    }
}

// ---------------------------------------------------------------------------
// Kernel 2: gather — materialize A in pair-interleaved layout
//   element (kg, pos) -> g_A[chunk*32*MTOT + pr*2*MTOT + pos*2 + slot]
//   chunk = kg>>5; r = kg&31; pr = (r>>3)*4 + (r&3); slot = (r>>2)&1
// ---------------------------------------------------------------------------
__global__ __launch_bounds__(1024) void gather_kernel(const float* __restrict__ x)
{
    const int tid  = threadIdx.x;
    const int warp = tid >> 5;
    const int lane = tid & 31;
    const int pw   = warp & 3;
    const int cs   = warp >> 2;
    const int pos  = blockIdx.x * 128 + pw * 32 + lane;
    const int b    = pos >> 12;
    const float* xb = x + (size_t)b * CC * HWS;

#pragma unroll
    for (int k = 0; k < 9; k++) {
        const float4 wv = g_mw[pos * NP + k];
        const int4   iv = g_mi[pos * NP + k];
        const int chunk = k * 8 + cs;            // kg0 = chunk*32, r = j
        float* cbase = g_A + (size_t)chunk * 32 * MTOT + (size_t)pos * 2;
        const float* xp = xb + (size_t)(cs * 32) * HWS;
#pragma unroll 8
        for (int j = 0; j < 32; j++) {
            const int pr   = ((j >> 3) << 2) + (j & 3);
            const int slot = (j >> 2) & 1;
            cbase[(size_t)pr * 2 * MTOT + slot] =
                tf32r(dot4(wv, xp + (size_t)j * HWS, iv));
        }
    }
}

// ---------------------------------------------------------------------------
// Kernel 3: dense tf32 GEMM, 3-stage cp.async pipeline
//   A smem pair-interleaved [16 pr][264] (LDS.64 frags, conflict-free)
//   B smem [256][40] pair-interleaved (LDS.64 frags)
// ---------------------------------------------------------------------------
__global__ void __launch_bounds__(NTH, 1) gemm_kernel(float* __restrict__ out)
{
    extern __shared__ char smem[];

    const int tid  = threadIdx.x;
    const int wid  = tid >> 5;
    const int lane = tid & 31;
    const int gid  = lane >> 2;
    const int tig  = lane & 3;
    const int p0   = blockIdx.x * MT;
    const int b    = p0 >> 12;
    const int m0   = p0;

    const int mBase = (wid & 3) * 32;
    const int nBase = (wid >> 2) * 64;

    auto issue_stage = [&](int i, int s) {
        char* sa = smem + s * SA_BYTES;
        char* sb = smem + SM_SB0 + s * SB_BYTES;
        const float* aChunk = g_A + (size_t)i * 32 * MTOT;
        const size_t kg0 = (size_t)i * 32;
        // A: 16 pair-rows x 256 floats (m interleaved with slot)
#pragma unroll
        for (int r = 0; r < 2; r++) {
            int id = tid + r * NTH;
            int pr = id >> 6;
            int q  = id & 63;
            cpa16(sa + pr * (PRST * 4) + q * 16,
                  aChunk + (size_t)pr * 2 * MTOT + (size_t)m0 * 2 + q * 4);
        }
        // B: 256 rows x 32 floats (pair-interleaved in global)
#pragma unroll
        for (int r = 0; r < 4; r++) {
            int id = tid + r * NTH;
            int nr = id >> 3;
            int q  = id & 7;
            cpa16(sb + nr * (BST * 4) + q * 16,
                  g_wB2 + (size_t)nr * KTOT + kg0 + q * 4);
        }
        cpa_commit();
    };

    float acc[2][8][4];
#pragma unroll
    for (int mf = 0; mf < 2; mf++)
#pragma unroll
        for (int nf = 0; nf < 8; nf++)
#pragma unroll
            for (int r = 0; r < 4; r++) acc[mf][nf][r] = 0.f;

    issue_stage(0, 0);
    issue_stage(1, 1);

    for (int i = 0; i < NCHUNK; i++) {
        const int s = i % NSTAGE;
        cpa_wait_group<1>();
        __syncthreads();

        if (i + 2 < NCHUNK) issue_stage(i + 2, (i + 2) % NSTAGE);
        else                cpa_commit();

        const float* sAf = (const float*)(smem + s * SA_BYTES);
        const float* sBf = (const float*)(smem + SM_SB0 + s * SB_BYTES);
#pragma unroll
        for (int ks = 0; ks < 4; ks++) {
            const int pr = ks * 4 + tig;
            uint32_t a[2][4], bfrag[8][2];
#pragma unroll
            for (int mf = 0; mf < 2; mf++) {
                int m = mBase + mf * 16 + gid;
                float2 v0 = *(const float2*)&sAf[pr * PRST + m * 2];       // (m,k0),(m,k0+4)
                float2 v1 = *(const float2*)&sAf[pr * PRST + (m + 8) * 2]; // (m+8,k0),(m+8,k0+4)
                a[mf][0] = __float_as_uint(v0.x);
                a[mf][1] = __float_as_uint(v1.x);
                a[mf][2] = __float_as_uint(v0.y);
                a[mf][3] = __float_as_uint(v1.y);
            }
#pragma unroll
            for (int nf = 0; nf < 8; nf++) {
                int n = nBase + nf * 8 + gid;
                float2 bv = *(const float2*)&sBf[n * BST + ks * 8 + 2 * tig];
                bfrag[nf][0] = __float_as_uint(bv.x);
                bfrag[nf][1] = __float_as_uint(bv.y);
            }
#pragma unroll
            for (int mf = 0; mf < 2; mf++)
#pragma unroll
                for (int nf = 0; nf < 8; nf++)
                    mma_tf32(acc[mf][nf], a[mf], bfrag[nf]);
        }
    }

    // ---- epilogue ----
    {
        const int hw0 = p0 & 4095;
        float* ob = out + (size_t)b * OPL * HWS + hw0;
#pragma unroll
        for (int mf = 0; mf < 2; mf++) {
            int m = mBase + mf * 16 + gid;
#pragma unroll
            for (int nf = 0; nf < 8; nf++) {
                int n = nBase + nf * 8 + 2 * tig;
                ob[(size_t)n * HWS + m]           = acc[mf][nf][0];
                ob[(size_t)(n + 1) * HWS + m]     = acc[mf][nf][1];
                ob[(size_t)n * HWS + m + 8]       = acc[mf][nf][2];
                ob[(size_t)(n + 1) * HWS + m + 8] = acc[mf][nf][3];
            }
        }
    }
}

// ---------------------------------------------------------------------------
extern "C" void kernel_launch(void* const* d_in, const int* in_sizes, int n_in,
                              void* d_out, int out_size)
{
    const float* x      = (const float*)d_in[0];   // (4,256,64,64)
    const float* w_p    = (const float*)d_in[1];   // (18,256,3,3)
    const float* w_conv = (const float*)d_in[2];   // (256,256,3,3)
    float* out = (float*)d_out;                    // (4,256,64,64)

    cudaFuncSetAttribute(gemm_kernel, cudaFuncAttributeMaxDynamicSharedMemorySize, SM_TOTAL);

    const int permBlocks = (OPL * KTOT + 511) / 512;
    prep_kernel<<<128 + permBlocks, 512>>>(x, w_p, w_conv);
    gather_kernel<<<MTOT / 128, 1024>>>(x);
    gemm_kernel<<<MTOT / MT, NTH, SM_TOTAL>>>(out);
}

// round 13
// speedup vs baseline: 1.2781x; 1.2102x over previous
#include <cuda_runtime.h>
#include <cstdint>

#define BB   4
#define CC   256
#define HH   64
#define WW   64
#define HWS  4096
#define NP   9
#define OCH  18
#define OPL  256
#define KTOT 2304
#define MTOT 16384        // B*H*W

#define MT     128        // GEMM M tile
#define NCHUNK 72         // K chunks of 32, kg' = k*256 + c ordering
#define NTH    512
#define PRST   264        // sA pair-row stride (floats)
#define BST    40         // sB row stride (floats)
#define NSTAGE 3

// ---- dynamic smem for GEMM: 3 x (A 16x264 + B 256x40) ----
#define SA_BYTES (16 * PRST * 4)           // 16896
#define SB_BYTES (256 * BST * 4)           // 40960
#define SM_SB0   (NSTAGE * SA_BYTES)       // 50688
#define SM_TOTAL (NSTAGE * (SA_BYTES + SB_BYTES))   // 173568

__device__ float4 g_mw[BB * HWS * NP];
__device__ int4   g_mi[BB * HWS * NP];
__device__ float  g_wB2[OPL * KTOT];       // [n][chunk*32 + pairperm], tf32
// A pair-interleaved: [chunk][pr(16)][pos][slot(2)], tf32 samples
__device__ float  g_A[(size_t)KTOT * MTOT];

typedef unsigned long long ull;

// ---------------------------------------------------------------------------
// helpers
// ---------------------------------------------------------------------------
__device__ __forceinline__ float tf32r(float x) {
    uint32_t u;
    asm("cvt.rna.tf32.f32 %0, %1;" : "=r"(u) : "f"(x));
    return __uint_as_float(u);
}
__device__ __forceinline__ ull dup2(float v) {
    ull r; asm("mov.b64 %0, {%1, %1};" : "=l"(r) : "f"(v)); return r;
}
__device__ __forceinline__ ull pack2(float a, float b) {
    ull r; asm("mov.b64 %0, {%1, %2};" : "=l"(r) : "f"(a), "f"(b)); return r;
}
__device__ __forceinline__ void fma2(ull& acc, ull a, ull b) {
    asm("fma.rn.f32x2 %0, %1, %2, %0;" : "+l"(acc) : "l"(a), "l"(b));
}
union UPair { ull u; float2 f; };

__device__ __forceinline__ uint32_t smem_u32(const void* p) {
    return (uint32_t)__cvta_generic_to_shared(p);
}
__device__ __forceinline__ void cpa16(void* dst, const void* src) {
    asm volatile("cp.async.cg.shared.global [%0], [%1], 16;"
                 :: "r"(smem_u32(dst)), "l"(src));
}
__device__ __forceinline__ void cpa_commit() {
    asm volatile("cp.async.commit_group;" ::: "memory");
}
template <int N>
__device__ __forceinline__ void cpa_wait_group() {
    asm volatile("cp.async.wait_group %0;" :: "n"(N) : "memory");
}

__device__ __forceinline__ void mma_tf32(float* c, const uint32_t* a, const uint32_t* b) {
    asm volatile(
        "mma.sync.aligned.m16n8k8.row.col.f32.tf32.tf32.f32 "
        "{%0,%1,%2,%3}, {%4,%5,%6,%7}, {%8,%9}, {%0,%1,%2,%3};"
        : "+f"(c[0]), "+f"(c[1]), "+f"(c[2]), "+f"(c[3])
        : "r"(a[0]), "r"(a[1]), "r"(a[2]), "r"(a[3]), "r"(b[0]), "r"(b[1]));
}

__device__ __forceinline__ float dot4(float4 wv, const float* xp, int4 iv) {
    return wv.x * xp[iv.x] + wv.y * xp[iv.y] + wv.z * xp[iv.z] + wv.w * xp[iv.w];
}

// ---------------------------------------------------------------------------
// Kernel 1 (fused prep):
//   blocks [0,256):  offsets conv + metadata. 64 positions x 8 channel-parts.
//   blocks [256+):   w_conv permute+pair-interleave+tf32 -> g_wB2
// ---------------------------------------------------------------------------
__global__ __launch_bounds__(512) void prep_kernel(const float* __restrict__ x,
                                                   const float* __restrict__ w_p,
                                                   const float* __restrict__ wc)
{
    if (blockIdx.x >= 256) {
        int idx = (blockIdx.x - 256) * 512 + threadIdx.x;   // PHYSICAL slot
        if (idx < OPL * KTOT) {
            int n  = idx / KTOT;
            int rp = idx - n * KTOT;
            int chunk = rp >> 5;
            int p  = rp & 31;
            int g  = p >> 3;
            int pp = p & 7;
            int t  = (pp >> 1) + ((pp & 1) << 2);   // inverse of phys=2*(t&3)+(t>>2)
            int c  = (chunk & 7) * 32 + g * 8 + t;
            int k  = chunk >> 3;
            g_wB2[idx] = tf32r(wc[n * KTOT + c * 9 + k]);
        }
        return;
    }

    __shared__ ull s_mem[64 * 9 * 10];   // staging 5760 ull / reduce 8*64*9=4608 ull

    const int tid   = threadIdx.x;
    const int pos_l = tid & 63;
    const int part  = tid >> 6;                 // 0..7: channel eighth within blk
    const int pos   = blockIdx.x * 64 + pos_l;
    const int b = pos >> 12;
    const int h = (pos >> 6) & 63;
    const int w = pos & 63;
    const float* xb = x + (size_t)b * CC * HWS;

    ull accp[9];
#pragma unroll
    for (int i = 0; i < 9; i++) accp[i] = 0ull;

    for (int blk = 0; blk < 4; blk++) {
        __syncthreads();
        for (int i = tid; i < 64 * 81; i += 512) {
            int cl = i / 81;
            int r  = i % 81;
            int t  = r / 9;
            int op = r - t * 9;
            int c  = blk * 64 + cl;
            float w0 = w_p[((2 * op)     * CC + c) * 9 + t];
            float w1 = w_p[((2 * op + 1) * CC + c) * 9 + t];
            s_mem[(cl * 9 + t) * 10 + op] = pack2(w0, w1);
        }
        __syncthreads();

        for (int q = 0; q < 8; q++) {
            int cl = part * 8 + q;
            const float* xp = xb + (size_t)(blk * 64 + cl) * HWS;
            float xv[9];
#pragma unroll
            for (int dh = -1; dh <= 1; dh++) {
#pragma unroll
                for (int dw = -1; dw <= 1; dw++) {
                    int hh = h + dh, ww = w + dw;
                    float v = 0.f;
                    if (hh >= 0 && hh < HH && ww >= 0 && ww < WW) v = xp[hh * WW + ww];
                    xv[(dh + 1) * 3 + (dw + 1)] = v;
                }
            }
#pragma unroll
            for (int t = 0; t < 9; t++) {
                ull xd = dup2(xv[t]);
                const ulonglong2* wp4 = (const ulonglong2*)&s_mem[(cl * 9 + t) * 10];
                ulonglong2 p01 = wp4[0];
                ulonglong2 p23 = wp4[1];
                ulonglong2 p45 = wp4[2];
                ulonglong2 p67 = wp4[3];
                ull p8 = s_mem[(cl * 9 + t) * 10 + 8];
                fma2(accp[0], p01.x, xd);
                fma2(accp[1], p01.y, xd);
                fma2(accp[2], p23.x, xd);
                fma2(accp[3], p23.y, xd);
                fma2(accp[4], p45.x, xd);
                fma2(accp[5], p45.y, xd);
                fma2(accp[6], p67.x, xd);
                fma2(accp[7], p67.y, xd);
                fma2(accp[8], p8,    xd);
            }
        }
    }

    __syncthreads();
    ull* s_red = s_mem;   // [part][pos_l][9]
#pragma unroll
    for (int op = 0; op < 9; op++)
        s_red[(part * 64 + pos_l) * 9 + op] = accp[op];
    __syncthreads();

    if (tid < 64) {
        float acc[OCH];
#pragma unroll
        for (int op = 0; op < 9; op++) {
            float sx = 0.f, sy = 0.f;
#pragma unroll
            for (int pt = 0; pt < 8; pt++) {
                UPair u; u.u = s_red[(pt * 64 + tid) * 9 + op];
                sx += u.f.x; sy += u.f.y;
            }
            acc[2 * op]     = sx;
            acc[2 * op + 1] = sy;
        }
#pragma unroll
        for (int k = 0; k < 9; k++) {
            float rx = (float)(k / 3 - 1);
            float ry = (float)(k % 3 - 1);
            float px = acc[k]     + rx + (float)(h + 1);
            float py = acc[9 + k] + ry + (float)(w + 1);
            float fx = floorf(px), fy = floorf(py);
            float ltx = fminf(fmaxf(fx,       0.f), 63.f);
            float lty = fminf(fmaxf(fy,       0.f), 63.f);
            float rbx = fminf(fmaxf(fx + 1.f, 0.f), 63.f);
            float rby = fminf(fmaxf(fy + 1.f, 0.f), 63.f);
            float pxc = fminf(fmaxf(px,       0.f), 63.f);
            float pyc = fminf(fmaxf(py,       0.f), 63.f);
            float glt = (1.f + (ltx - pxc)) * (1.f + (lty - pyc));
            float grb = (1.f - (rbx - pxc)) * (1.f - (rby - pyc));
            float glb = (1.f + (ltx - pxc)) * (1.f - (rby - pyc));
            float grt = (1.f - (rbx - pxc)) * (1.f + (lty - pyc));
            int iltx = (int)ltx, ilty = (int)lty, irbx = (int)rbx, irby = (int)rby;
            g_mw[pos * 9 + k] = make_float4(glt, grb, glb, grt);
            g_mi[pos * 9 + k] = make_int4(iltx * WW + ilty,
                                          irbx * WW + irby,
                                          iltx * WW + irby,
                                          irbx * WW + ilty);
        }
    }
}

// ---------------------------------------------------------------------------
// Kernel 2: gather — pair-interleaved A with COALESCED float2 stores
//   thread computes both slots of a pair-row: channels j0 and j0+4
//   g_A float2 index: chunk*16*MTOT + pr*MTOT + pos
// ---------------------------------------------------------------------------
__global__ __launch_bounds__(1024) void gather_kernel(const float* __restrict__ x)
{
    const int tid  = threadIdx.x;
    const int warp = tid >> 5;
    const int lane = tid & 31;
    const int pw   = warp & 3;
    const int cs   = warp >> 2;
    const int pos  = blockIdx.x * 128 + pw * 32 + lane;
    const int b    = pos >> 12;
    const float* xb = x + (size_t)b * CC * HWS;

#pragma unroll
    for (int k = 0; k < 9; k++) {
        const float4 wv = g_mw[pos * NP + k];
        const int4   iv = g_mi[pos * NP + k];
        const int chunk = k * 8 + cs;
        float2* cb2 = (float2*)g_A + (size_t)chunk * 16 * MTOT + pos;
        const float* xp = xb + (size_t)(cs * 32) * HWS;
#pragma unroll 4
        for (int pr = 0; pr < 16; pr++) {
            const int j0 = ((pr >> 2) << 3) + (pr & 3);
            float2 v;
            v.x = tf32r(dot4(wv, xp + (size_t)j0 * HWS,       iv));
            v.y = tf32r(dot4(wv, xp + (size_t)(j0 + 4) * HWS, iv));
            cb2[(size_t)pr * MTOT] = v;
        }
    }
}

// ---------------------------------------------------------------------------
// Kernel 3: dense tf32 GEMM, 3-stage cp.async pipeline
//   A smem pair-interleaved [16 pr][264]; B [256][40] pair-interleaved
//   both fragment types are LDS.64, conflict-free
// ---------------------------------------------------------------------------
__global__ void __launch_bounds__(NTH, 1) gemm_kernel(float* __restrict__ out)
{
    extern __shared__ char smem[];

    const int tid  = threadIdx.x;
    const int wid  = tid >> 5;
    const int lane = tid & 31;
    const int gid  = lane >> 2;
    const int tig  = lane & 3;
    const int p0   = blockIdx.x * MT;
    const int b    = p0 >> 12;
    const int m0   = p0;

    const int mBase = (wid & 3) * 32;
    const int nBase = (wid >> 2) * 64;

    auto issue_stage = [&](int i, int s) {
        char* sa = smem + s * SA_BYTES;
        char* sb = smem + SM_SB0 + s * SB_BYTES;
        const float* aChunk = g_A + (size_t)i * 32 * MTOT;
        const size_t kg0 = (size_t)i * 32;
        // A: 16 pair-rows x 256 floats
#pragma unroll
        for (int r = 0; r < 2; r++) {
            int id = tid + r * NTH;
            int pr = id >> 6;
            int q  = id & 63;
            cpa16(sa + pr * (PRST * 4) + q * 16,
                  aChunk + (size_t)pr * 2 * MTOT + (size_t)m0 * 2 + q * 4);
        }
        // B: 256 rows x 32 floats
#pragma unroll
        for (int r = 0; r < 4; r++) {
            int id = tid + r * NTH;
            int nr = id >> 3;
            int q  = id & 7;
            cpa16(sb + nr * (BST * 4) + q * 16,
                  g_wB2 + (size_t)nr * KTOT + kg0 + q * 4);
        }
        cpa_commit();
    };

    float acc[2][8][4];
#pragma unroll
    for (int mf = 0; mf < 2; mf++)
#pragma unroll
        for (int nf = 0; nf < 8; nf++)
#pragma unroll
            for (int r = 0; r < 4; r++) acc[mf][nf][r] = 0.f;

    issue_stage(0, 0);
    issue_stage(1, 1);

    for (int i = 0; i < NCHUNK; i++) {
        const int s = i % NSTAGE;
        cpa_wait_group<1>();
        __syncthreads();

        if (i + 2 < NCHUNK) issue_stage(i + 2, (i + 2) % NSTAGE);
        else                cpa_commit();

        const float* sAf = (const float*)(smem + s * SA_BYTES);
        const float* sBf = (const float*)(smem + SM_SB0 + s * SB_BYTES);
#pragma unroll
        for (int ks = 0; ks < 4; ks++) {
            const int pr = ks * 4 + tig;
            uint32_t a[2][4], bfrag[8][2];
#pragma unroll
            for (int mf = 0; mf < 2; mf++) {
                int m = mBase + mf * 16 + gid;
                float2 v0 = *(const float2*)&sAf[pr * PRST + m * 2];
                float2 v1 = *(const float2*)&sAf[pr * PRST + (m + 8) * 2];
                a[mf][0] = __float_as_uint(v0.x);
                a[mf][1] = __float_as_uint(v1.x);
                a[mf][2] = __float_as_uint(v0.y);
                a[mf][3] = __float_as_uint(v1.y);
            }
#pragma unroll
            for (int nf = 0; nf < 8; nf++) {
                int n = nBase + nf * 8 + gid;
                float2 bv = *(const float2*)&sBf[n * BST + ks * 8 + 2 * tig];
                bfrag[nf][0] = __float_as_uint(bv.x);
                bfrag[nf][1] = __float_as_uint(bv.y);
            }
#pragma unroll
            for (int mf = 0; mf < 2; mf++)
#pragma unroll
                for (int nf = 0; nf < 8; nf++)
                    mma_tf32(acc[mf][nf], a[mf], bfrag[nf]);
        }
    }

    // ---- epilogue ----
    {
        const int hw0 = p0 & 4095;
        float* ob = out + (size_t)b * OPL * HWS + hw0;
#pragma unroll
        for (int mf = 0; mf < 2; mf++) {
            int m = mBase + mf * 16 + gid;
#pragma unroll
            for (int nf = 0; nf < 8; nf++) {
                int n = nBase + nf * 8 + 2 * tig;
                ob[(size_t)n * HWS + m]           = acc[mf][nf][0];
                ob[(size_t)(n + 1) * HWS + m]     = acc[mf][nf][1];
                ob[(size_t)n * HWS + m + 8]       = acc[mf][nf][2];
                ob[(size_t)(n + 1) * HWS + m + 8] = acc[mf][nf][3];
            }
        }
    }
}

// ---------------------------------------------------------------------------
extern "C" void kernel_launch(void* const* d_in, const int* in_sizes, int n_in,
                              void* d_out, int out_size)
{
    const float* x      = (const float*)d_in[0];   // (4,256,64,64)
    const float* w_p    = (const float*)d_in[1];   // (18,256,3,3)
    const float* w_conv = (const float*)d_in[2];   // (256,256,3,3)
    float* out = (float*)d_out;                    // (4,256,64,64)

    cudaFuncSetAttribute(gemm_kernel, cudaFuncAttributeMaxDynamicSharedMemorySize, SM_TOTAL);

    const int permBlocks = (OPL * KTOT + 511) / 512;
    prep_kernel<<<256 + permBlocks, 512>>>(x, w_p, w_conv);
    gather_kernel<<<MTOT / 128, 1024>>>(x);
    gemm_kernel<<<MTOT / MT, NTH, SM_TOTAL>>>(out);
}

// round 14
// speedup vs baseline: 1.6483x; 1.2897x over previous
#include <cuda_runtime.h>
#include <cuda_fp16.h>
#include <cstdint>

#define BB   4
#define CC   256
#define HH   64
#define WW   64
#define HWS  4096
#define NP   9
#define OCH  18
#define OPL  256
#define KTOT 2304
#define MTOT 16384        // B*H*W

#define MT     128        // GEMM M tile
#define NCHUNK 72         // chunks: (kernel point k, 32-channel group)
#define NTH    512
#define AS8    132        // sA row stride in 8B units (128 payload + 4 pad)
#define BS8    12         // sB row stride in 8B units (8 payload + 4 pad)
#define NSTAGE 3

// ---- dynamic smem for GEMM: 3 x (A 8x1056B + B 256x96B) ----
#define SA_BYTES (8 * AS8 * 8)             // 8448
#define SB_BYTES (256 * BS8 * 8)           // 24576
#define SM_SB0   (NSTAGE * SA_BYTES)       // 25344
#define SM_TOTAL (NSTAGE * (SA_BYTES + SB_BYTES))   // 99072

typedef unsigned long long ull;

__device__ float4 g_mw[BB * HWS * NP];
__device__ int4   g_mi[BB * HWS * NP];
__device__ __half g_wB[OPL * KTOT];        // [n][chunk*32 + phys-k], fp16
// A: [chunk][gt-row(8)][pos] of 8B = 4 fp16 {2t,2t+1,2t+8,2t+9}
__device__ ull    g_A2[(size_t)NCHUNK * 8 * MTOT];

// ---------------------------------------------------------------------------
// helpers
// ---------------------------------------------------------------------------
__device__ __forceinline__ ull dup2(float v) {
    ull r; asm("mov.b64 %0, {%1, %1};" : "=l"(r) : "f"(v)); return r;
}
__device__ __forceinline__ ull pack2(float a, float b) {
    ull r; asm("mov.b64 %0, {%1, %2};" : "=l"(r) : "f"(a), "f"(b)); return r;
}
__device__ __forceinline__ void fma2(ull& acc, ull a, ull b) {
    asm("fma.rn.f32x2 %0, %1, %2, %0;" : "+l"(acc) : "l"(a), "l"(b));
}
union UPair { ull u; float2 f; };

__device__ __forceinline__ uint32_t smem_u32(const void* p) {
    return (uint32_t)__cvta_generic_to_shared(p);
}
__device__ __forceinline__ void cpa16(void* dst, const void* src) {
    asm volatile("cp.async.cg.shared.global [%0], [%1], 16;"
                 :: "r"(smem_u32(dst)), "l"(src));
}
__device__ __forceinline__ void cpa_commit() {
    asm volatile("cp.async.commit_group;" ::: "memory");
}
template <int N>
__device__ __forceinline__ void cpa_wait_group() {
    asm volatile("cp.async.wait_group %0;" :: "n"(N) : "memory");
}

__device__ __forceinline__ void mma_f16(float* c, const uint32_t* a, const uint32_t* b) {
    asm volatile(
        "mma.sync.aligned.m16n8k16.row.col.f32.f16.f16.f32 "
        "{%0,%1,%2,%3}, {%4,%5,%6,%7}, {%8,%9}, {%0,%1,%2,%3};"
        : "+f"(c[0]), "+f"(c[1]), "+f"(c[2]), "+f"(c[3])
        : "r"(a[0]), "r"(a[1]), "r"(a[2]), "r"(a[3]), "r"(b[0]), "r"(b[1]));
}

__device__ __forceinline__ float dot4(float4 wv, const float* xp, int4 iv) {
    return wv.x * xp[iv.x] + wv.y * xp[iv.y] + wv.z * xp[iv.z] + wv.w * xp[iv.w];
}

// ---------------------------------------------------------------------------
// Kernel 1 (fused prep):
//   blocks [0,256):  offsets conv + metadata (64 pos x 8 channel-parts)
//   blocks [256+):   w_conv permute -> fp16 g_wB[n][chunk*32 + phys]
//     phys p: g=p>>4, p16=p&15, t=p16>>2, j=p16&3
//     klocal16 = (j<2) ? 2t+j : 8+2t+(j-2); c = (chunk&7)*32 + g*16 + klocal16
// ---------------------------------------------------------------------------
__global__ __launch_bounds__(512) void prep_kernel(const float* __restrict__ x,
                                                   const float* __restrict__ w_p,
                                                   const float* __restrict__ wc)
{
    if (blockIdx.x >= 256) {
        int idx = (blockIdx.x - 256) * 512 + threadIdx.x;
        if (idx < OPL * KTOT) {
            int n  = idx / KTOT;
            int rp = idx - n * KTOT;
            int chunk = rp >> 5;
            int p   = rp & 31;
            int g   = p >> 4;
            int p16 = p & 15;
            int t   = p16 >> 2;
            int j   = p16 & 3;
            int kl  = (j < 2) ? (2 * t + j) : (8 + 2 * t + (j - 2));
            int c   = (chunk & 7) * 32 + g * 16 + kl;
            int k   = chunk >> 3;
            g_wB[idx] = __float2half_rn(wc[n * KTOT + c * 9 + k]);
        }
        return;
    }

    __shared__ ull s_mem[64 * 9 * 10];

    const int tid   = threadIdx.x;
    const int pos_l = tid & 63;
    const int part  = tid >> 6;                 // 0..7
    const int pos   = blockIdx.x * 64 + pos_l;
    const int b = pos >> 12;
    const int h = (pos >> 6) & 63;
    const int w = pos & 63;
    const float* xb = x + (size_t)b * CC * HWS;

    ull accp[9];
#pragma unroll
    for (int i = 0; i < 9; i++) accp[i] = 0ull;

    for (int blk = 0; blk < 4; blk++) {
        __syncthreads();
        for (int i = tid; i < 64 * 81; i += 512) {
            int cl = i / 81;
            int r  = i % 81;
            int t  = r / 9;
            int op = r - t * 9;
            int c  = blk * 64 + cl;
            float w0 = w_p[((2 * op)     * CC + c) * 9 + t];
            float w1 = w_p[((2 * op + 1) * CC + c) * 9 + t];
            s_mem[(cl * 9 + t) * 10 + op] = pack2(w0, w1);
        }
        __syncthreads();

        for (int q = 0; q < 8; q++) {
            int cl = part * 8 + q;
            const float* xp = xb + (size_t)(blk * 64 + cl) * HWS;
            float xv[9];
#pragma unroll
            for (int dh = -1; dh <= 1; dh++) {
#pragma unroll
                for (int dw = -1; dw <= 1; dw++) {
                    int hh = h + dh, ww = w + dw;
                    float v = 0.f;
                    if (hh >= 0 && hh < HH && ww >= 0 && ww < WW) v = xp[hh * WW + ww];
                    xv[(dh + 1) * 3 + (dw + 1)] = v;
                }
            }
#pragma unroll
            for (int t = 0; t < 9; t++) {
                ull xd = dup2(xv[t]);
                const ulonglong2* wp4 = (const ulonglong2*)&s_mem[(cl * 9 + t) * 10];
                ulonglong2 p01 = wp4[0];
                ulonglong2 p23 = wp4[1];
                ulonglong2 p45 = wp4[2];
                ulonglong2 p67 = wp4[3];
                ull p8 = s_mem[(cl * 9 + t) * 10 + 8];
                fma2(accp[0], p01.x, xd);
                fma2(accp[1], p01.y, xd);
                fma2(accp[2], p23.x, xd);
                fma2(accp[3], p23.y, xd);
                fma2(accp[4], p45.x, xd);
                fma2(accp[5], p45.y, xd);
                fma2(accp[6], p67.x, xd);
                fma2(accp[7], p67.y, xd);
                fma2(accp[8], p8,    xd);
            }
        }
    }

    __syncthreads();
    ull* s_red = s_mem;
#pragma unroll
    for (int op = 0; op < 9; op++)
        s_red[(part * 64 + pos_l) * 9 + op] = accp[op];
    __syncthreads();

    if (tid < 64) {
        float acc[OCH];
#pragma unroll
        for (int op = 0; op < 9; op++) {
            float sx = 0.f, sy = 0.f;
#pragma unroll
            for (int pt = 0; pt < 8; pt++) {
                UPair u; u.u = s_red[(pt * 64 + tid) * 9 + op];
                sx += u.f.x; sy += u.f.y;
            }
            acc[2 * op]     = sx;
            acc[2 * op + 1] = sy;
        }
#pragma unroll
        for (int k = 0; k < 9; k++) {
            float rx = (float)(k / 3 - 1);
            float ry = (float)(k % 3 - 1);
            float px = acc[k]     + rx + (float)(h + 1);
            float py = acc[9 + k] + ry + (float)(w + 1);
            float fx = floorf(px), fy = floorf(py);
            float ltx = fminf(fmaxf(fx,       0.f), 63.f);
            float lty = fminf(fmaxf(fy,       0.f), 63.f);
            float rbx = fminf(fmaxf(fx + 1.f, 0.f), 63.f);
            float rby = fminf(fmaxf(fy + 1.f, 0.f), 63.f);
            float pxc = fminf(fmaxf(px,       0.f), 63.f);
            float pyc = fminf(fmaxf(py,       0.f), 63.f);
            float glt = (1.f + (ltx - pxc)) * (1.f + (lty - pyc));
            float grb = (1.f - (rbx - pxc)) * (1.f - (rby - pyc));
            float glb = (1.f + (ltx - pxc)) * (1.f - (rby - pyc));
            float grt = (1.f - (rbx - pxc)) * (1.f + (lty - pyc));
            int iltx = (int)ltx, ilty = (int)lty, irbx = (int)rbx, irby = (int)rby;
            g_mw[pos * 9 + k] = make_float4(glt, grb, glb, grt);
            g_mi[pos * 9 + k] = make_int4(iltx * WW + ilty,
                                          irbx * WW + irby,
                                          iltx * WW + irby,
                                          irbx * WW + ilty);
        }
    }
}

// ---------------------------------------------------------------------------
// Kernel 2: gather — fp16 A in fragment-ready layout
//   row (chunk, g*4+t) holds per pos 8B = fp16 of channels
//   {base+2t, base+2t+1, base+2t+8, base+2t+9}, base = cs*32 + g*16
//   Stores: 8B per lane, consecutive pos -> fully coalesced.
// ---------------------------------------------------------------------------
__global__ __launch_bounds__(1024) void gather_kernel(const float* __restrict__ x)
{
    const int tid  = threadIdx.x;
    const int warp = tid >> 5;
    const int lane = tid & 31;
    const int pw   = warp & 3;
    const int cs   = warp >> 2;        // 0..7: 32-channel group
    const int pos  = blockIdx.x * 128 + pw * 32 + lane;
    const int b    = pos >> 12;
    const float* xb = x + (size_t)b * CC * HWS;

    for (int k = 0; k < 9; k++) {
        const float4 wv = g_mw[pos * NP + k];
        const int4   iv = g_mi[pos * NP + k];
        const int chunk = k * 8 + cs;
        ull* cb = g_A2 + (size_t)chunk * 8 * MTOT + pos;
        const float* xp = xb + (size_t)(cs * 32) * HWS;
#pragma unroll
        for (int gt = 0; gt < 8; gt++) {
            const int g = gt >> 2;
            const int t = gt & 3;
            const float* xc = xp + (size_t)(g * 16 + 2 * t) * HWS;
            float f0 = dot4(wv, xc,               iv);
            float f1 = dot4(wv, xc + HWS,         iv);
            float f2 = dot4(wv, xc + 8 * HWS,     iv);
            float f3 = dot4(wv, xc + 9 * HWS,     iv);
            __half2 h01 = __floats2half2_rn(f0, f1);
            __half2 h23 = __floats2half2_rn(f2, f3);
            uint2 st;
            st.x = *(uint32_t*)&h01;
            st.y = *(uint32_t*)&h23;
            *(uint2*)(cb + (size_t)gt * MTOT) = st;
        }
    }
}

// ---------------------------------------------------------------------------
// Kernel 3: dense fp16 GEMM (m16n8k16, f32 accum), 3-stage cp.async pipeline
//   A smem [8 gt][AS8] of 8B; B smem [256 n][BS8] of 8B — both LDS.64 frags,
//   conflict-free (A: addr8≡4*tig+gid; B: addr8≡12*gid+tig, bijective/phase)
// ---------------------------------------------------------------------------
__global__ void __launch_bounds__(NTH, 1) gemm_kernel(float* __restrict__ out)
{
    extern __shared__ char smem[];

    const int tid  = threadIdx.x;
    const int wid  = tid >> 5;
    const int lane = tid & 31;
    const int gid  = lane >> 2;
    const int tig  = lane & 3;
    const int p0   = blockIdx.x * MT;
    const int b    = p0 >> 12;
    const int m0   = p0;

    const int mBase = (wid & 3) * 32;
    const int nBase = (wid >> 2) * 64;

    auto issue_stage = [&](int i, int s) {
        char* sa = smem + s * SA_BYTES;
        char* sb = smem + SM_SB0 + s * SB_BYTES;
        const ull* aChunk = g_A2 + (size_t)i * 8 * MTOT + m0;
        const __half* bChunk = g_wB + i * 32;
        // A: 8 rows x 1024B payload -> 512 cpa16 (1/thread)
        {
            int r = tid >> 6;
            int q = tid & 63;
            cpa16(sa + r * (AS8 * 8) + q * 16, aChunk + (size_t)r * MTOT + q * 2);
        }
        // B: 256 rows x 64B payload -> 1024 cpa16 (2/thread)
#pragma unroll
        for (int r = 0; r < 2; r++) {
            int id = tid + r * NTH;
            int nr = id >> 2;
            int q  = id & 3;
            cpa16(sb + nr * (BS8 * 8) + q * 16, bChunk + (size_t)nr * KTOT + q * 8);
        }
        cpa_commit();
    };

    float acc[2][8][4];
#pragma unroll
    for (int mf = 0; mf < 2; mf++)
#pragma unroll
        for (int nf = 0; nf < 8; nf++)
#pragma unroll
            for (int r = 0; r < 4; r++) acc[mf][nf][r] = 0.f;

    issue_stage(0, 0);
    issue_stage(1, 1);

    for (int i = 0; i < NCHUNK; i++) {
        const int s = i % NSTAGE;
        cpa_wait_group<1>();
        __syncthreads();

        if (i + 2 < NCHUNK) issue_stage(i + 2, (i + 2) % NSTAGE);
        else                cpa_commit();

        const ull* sA8 = (const ull*)(smem + s * SA_BYTES);
        const ull* sB8 = (const ull*)(smem + SM_SB0 + s * SB_BYTES);
#pragma unroll
        for (int g = 0; g < 2; g++) {          // two k16 steps per chunk
            uint32_t a[2][4], bfrag[8][2];
#pragma unroll
            for (int mf = 0; mf < 2; mf++) {
                int m = mBase + mf * 16 + gid;
                uint2 v0 = *(const uint2*)&sA8[(g * 4 + tig) * AS8 + m];
                uint2 v1 = *(const uint2*)&sA8[(g * 4 + tig) * AS8 + m + 8];
                a[mf][0] = v0.x;   // (m,   k0..k0+1)
                a[mf][1] = v1.x;   // (m+8, k0..k0+1)
                a[mf][2] = v0.y;   // (m,   k0+8..9)
                a[mf][3] = v1.y;   // (m+8, k0+8..9)
            }
#pragma unroll
            for (int nf = 0; nf < 8; nf++) {
                int n = nBase + nf * 8 + gid;
                uint2 bv = *(const uint2*)&sB8[n * BS8 + g * 4 + tig];
                bfrag[nf][0] = bv.x;
                bfrag[nf][1] = bv.y;
            }
#pragma unroll
            for (int mf = 0; mf < 2; mf++)
#pragma unroll
                for (int nf = 0; nf < 8; nf++)
                    mma_f16(acc[mf][nf], a[mf], bfrag[nf]);
        }
    }

    // ---- epilogue ----
    {
        const int hw0 = p0 & 4095;
        float* ob = out + (size_t)b * OPL * HWS + hw0;
#pragma unroll
        for (int mf = 0; mf < 2; mf++) {
            int m = mBase + mf * 16 + gid;
#pragma unroll
            for (int nf = 0; nf < 8; nf++) {
                int n = nBase + nf * 8 + 2 * tig;
                ob[(size_t)n * HWS + m]           = acc[mf][nf][0];
                ob[(size_t)(n + 1) * HWS + m]     = acc[mf][nf][1];
                ob[(size_t)n * HWS + m + 8]       = acc[mf][nf][2];
                ob[(size_t)(n + 1) * HWS + m + 8] = acc[mf][nf][3];
            }
        }
    }
}

// ---------------------------------------------------------------------------
extern "C" void kernel_launch(void* const* d_in, const int* in_sizes, int n_in,
                              void* d_out, int out_size)
{
    const float* x      = (const float*)d_in[0];   // (4,256,64,64)
    const float* w_p    = (const float*)d_in[1];   // (18,256,3,3)
    const float* w_conv = (const float*)d_in[2];   // (256,256,3,3)
    float* out = (float*)d_out;                    // (4,256,64,64)

    cudaFuncSetAttribute(gemm_kernel, cudaFuncAttributeMaxDynamicSharedMemorySize, SM_TOTAL);

    const int permBlocks = (OPL * KTOT + 511) / 512;
    prep_kernel<<<256 + permBlocks, 512>>>(x, w_p, w_conv);
    gather_kernel<<<MTOT / 128, 1024>>>(x);
    gemm_kernel<<<MTOT / MT, NTH, SM_TOTAL>>>(out);
}